// round 1
// baseline (speedup 1.0000x reference)
#include <cuda_runtime.h>
#include <math.h>

#define NN 20000
#define FF 8
#define PP 12
#define OO 32
#define EE 320000
#define FP (FF*PP)   // 96 floats per node

// ---- scratch (static device globals; no allocation allowed) ----
__device__ __align__(16) float g_agg[NN * FP];   // aggregated raw features [N][F][P]
__device__ float g_dinv[NN];                     // deg -> d^-1/2 (in place)
__device__ float g_cwz[FF * OO];                 // fused  Wz @ Lz^T   [F][O]
__device__ float g_cwh[FF * OO];                 // fused  Wh @ Lh^T   [F][O]
__device__ float g_cbz[OO];                      // fused  bz @ Lz^T + lz_b
__device__ float g_cbh[OO];
__device__ float g_probs[PP];                    // softmax(att)

// ---------------------------------------------------------------------------
// K0: fold GCN weights into the GRU linears (H == 0 makes this exact),
//     and compute softmax(att). One block, 512 threads, trivial cost.
// ---------------------------------------------------------------------------
__global__ void prep_kernel(const float* __restrict__ Wz, const float* __restrict__ bz,
                            const float* __restrict__ Wh, const float* __restrict__ bh,
                            const float* __restrict__ lzw, const float* __restrict__ lzb,
                            const float* __restrict__ lhw, const float* __restrict__ lhb,
                            const float* __restrict__ att) {
    int t = threadIdx.x;
    if (t < 256) {                       // W'_z[f][o] = sum_k Wz[f][k] * lzw[o][k]
        int f = t >> 5, o = t & 31;
        float s = 0.f;
        #pragma unroll
        for (int k = 0; k < 32; ++k) s = fmaf(Wz[f * 32 + k], lzw[o * 64 + k], s);
        g_cwz[t] = s;
    } else {                             // W'_h
        int i = t - 256;
        int f = i >> 5, o = i & 31;
        float s = 0.f;
        #pragma unroll
        for (int k = 0; k < 32; ++k) s = fmaf(Wh[f * 32 + k], lhw[o * 64 + k], s);
        g_cwh[i] = s;
    }
    if (t < 32) {                        // b'_z[o] = lz_b[o] + sum_k bz[k]*lzw[o][k]
        float s = lzb[t];
        #pragma unroll
        for (int k = 0; k < 32; ++k) s = fmaf(bz[k], lzw[t * 64 + k], s);
        g_cbz[t] = s;
    } else if (t < 64) {
        int o = t - 32;
        float s = lhb[o];
        #pragma unroll
        for (int k = 0; k < 32; ++k) s = fmaf(bh[k], lhw[o * 64 + k], s);
        g_cbh[o] = s;
    }
    if (t == 0) {                        // softmax over 12 logits
        float m = att[0];
        for (int p = 1; p < PP; ++p) m = fmaxf(m, att[p]);
        float e[PP], sum = 0.f;
        for (int p = 0; p < PP; ++p) { e[p] = __expf(att[p] - m); sum += e[p]; }
        float inv = 1.f / sum;
        for (int p = 0; p < PP; ++p) g_probs[p] = e[p] * inv;
    }
}

// ---------------------------------------------------------------------------
// K1: zero agg, init deg = 1 (self-loop)
// ---------------------------------------------------------------------------
__global__ void init_kernel() {
    int i = blockIdx.x * blockDim.x + threadIdx.x;
    int stride = gridDim.x * blockDim.x;
    for (int j = i; j < NN * FP; j += stride) g_agg[j] = 0.f;
    for (int j = i; j < NN; j += stride)      g_dinv[j] = 1.f;
}

// K2: in-degree accumulation
__global__ void deg_kernel(const int* __restrict__ ei) {
    int e = blockIdx.x * blockDim.x + threadIdx.x;
    if (e < EE) atomicAdd(&g_dinv[ei[EE + e]], 1.f);
}

// K3: deg -> d^-1/2 (deg >= 1 always, thanks to self loop)
__global__ void dinv_kernel() {
    int i = blockIdx.x * blockDim.x + threadIdx.x;
    if (i < NN) g_dinv[i] = rsqrtf(g_dinv[i]);
}

// ---------------------------------------------------------------------------
// K4: edge aggregation of RAW features (F*P = 96 floats, 24 x float4)
//     one warp per edge, lanes 0..23 active, red.global.add.v4 (sm_90+)
// ---------------------------------------------------------------------------
__global__ void edge_agg_kernel(const float* __restrict__ x, const int* __restrict__ ei) {
    int gid = blockIdx.x * blockDim.x + threadIdx.x;
    int e = gid >> 5;
    int lane = gid & 31;
    if (e >= EE || lane >= 24) return;
    int s = __ldg(&ei[e]);
    int d = __ldg(&ei[EE + e]);
    float w = g_dinv[s] * g_dinv[d];
    float4 v = __ldg(((const float4*)x) + (size_t)s * 24 + lane);
    v.x *= w; v.y *= w; v.z *= w; v.w *= w;
    float* a = g_agg + (size_t)d * FP + lane * 4;
    asm volatile("red.global.add.v4.f32 [%0], {%1, %2, %3, %4};"
                 :: "l"(a), "f"(v.x), "f"(v.y), "f"(v.z), "f"(v.w) : "memory");
}

// ---------------------------------------------------------------------------
// K5: per-node fused GRU + temporal attention + readout. One warp per node,
//     lane = output channel o (O = 32 == warp size).
// ---------------------------------------------------------------------------
__global__ void node_kernel(const float* __restrict__ x,
                            const float* __restrict__ out_w,
                            const float* __restrict__ out_b,
                            float* __restrict__ out) {
    __shared__ float buf[8][FP];   // 8 warps/block
    int warp = threadIdx.x >> 5;
    int lane = threadIdx.x & 31;
    int node = blockIdx.x * 8 + warp;
    if (node >= NN) return;

    float di = g_dinv[node];
    float sn = di * di;            // self-loop norm

    if (lane < 24) {               // stage agg + self-loop contribution to smem
        float4 av = ((const float4*)g_agg)[(size_t)node * 24 + lane];
        float4 xv = __ldg(((const float4*)x) + (size_t)node * 24 + lane);
        av.x = fmaf(xv.x, sn, av.x);
        av.y = fmaf(xv.y, sn, av.y);
        av.z = fmaf(xv.z, sn, av.z);
        av.w = fmaf(xv.w, sn, av.w);
        ((float4*)buf[warp])[lane] = av;
    }
    __syncwarp();

    float wz[FF], wh[FF];
    #pragma unroll
    for (int f = 0; f < FF; ++f) {
        wz[f] = g_cwz[f * OO + lane];
        wh[f] = g_cwh[f * OO + lane];
    }
    float bz_ = g_cbz[lane];
    float bh_ = g_cbh[lane];

    float hacc = 0.f;
    #pragma unroll
    for (int p = 0; p < PP; ++p) {
        float z = bz_, h = bh_;
        #pragma unroll
        for (int f = 0; f < FF; ++f) {
            float v = buf[warp][f * PP + p];   // broadcast LDS
            z = fmaf(v, wz[f], z);
            h = fmaf(v, wh[f], h);
        }
        float Z = 1.f / (1.f + __expf(-z));                 // sigmoid
        float T = 2.f / (1.f + __expf(-2.f * h)) - 1.f;     // tanh
        hacc = fmaf(g_probs[p], (1.f - Z) * T, hacc);       // Hp = (1-Z)*Ht, weighted
    }
    float hr = fmaxf(hacc, 0.f);   // relu

    // out[node][p] = sum_o hr[o] * out_w[p][o] + out_b[p]
    #pragma unroll
    for (int p = 0; p < PP; ++p) {
        float v = hr * __ldg(&out_w[p * OO + lane]);
        v += __shfl_xor_sync(0xffffffffu, v, 16);
        v += __shfl_xor_sync(0xffffffffu, v, 8);
        v += __shfl_xor_sync(0xffffffffu, v, 4);
        v += __shfl_xor_sync(0xffffffffu, v, 2);
        v += __shfl_xor_sync(0xffffffffu, v, 1);
        if (lane == 0) out[node * PP + p] = v + __ldg(&out_b[p]);
    }
}

// ---------------------------------------------------------------------------
extern "C" void kernel_launch(void* const* d_in, const int* in_sizes, int n_in,
                              void* d_out, int out_size) {
    const float* x    = (const float*)d_in[0];
    const int*   ei   = (const int*)  d_in[1];
    const float* Wz   = (const float*)d_in[2];
    const float* bz   = (const float*)d_in[3];
    // d_in[4], d_in[5]: Wr, br  — unused (reset gate is dead code: H == 0)
    const float* Wh   = (const float*)d_in[6];
    const float* bh   = (const float*)d_in[7];
    const float* lzw  = (const float*)d_in[8];
    const float* lzb  = (const float*)d_in[9];
    // d_in[10], d_in[11]: lr_w, lr_b — unused
    const float* lhw  = (const float*)d_in[12];
    const float* lhb  = (const float*)d_in[13];
    const float* att  = (const float*)d_in[14];
    const float* outw = (const float*)d_in[15];
    const float* outb = (const float*)d_in[16];
    float* out = (float*)d_out;

    prep_kernel<<<1, 512>>>(Wz, bz, Wh, bh, lzw, lzb, lhw, lhb, att);
    init_kernel<<<1024, 256>>>();
    deg_kernel<<<(EE + 255) / 256, 256>>>(ei);
    dinv_kernel<<<(NN + 255) / 256, 256>>>();
    edge_agg_kernel<<<(EE * 32 + 255) / 256, 256>>>(x, ei);
    node_kernel<<<(NN + 7) / 8, 256>>>(x, outw, outb, out);
}